// round 9
// baseline (speedup 1.0000x reference)
#include <cuda_runtime.h>
#include <cuda_fp16.h>
#include <cstdint>

#define B_   8
#define N_   2048
#define DIN  256
#define HID  64
#define TI   128
#define CH   32
#define NCH  (N_ / CH)
#define L2E  1.4426950408889634f

// dynamic SMEM layout for gat_main (6-slot ring)
#define NSLOT   6
#define SLOT_A  (128 * 144)                 // adj tile: 128 rows x 32 ints, 144B-padded
#define AOFF    0
#define A_END   (NSLOT * SLOT_A)            // 110592
#define SLOT_B  (32 * 144)                  // B tile: 32 nodes x 64 fp16, 144B-padded
#define BOFF    A_END
#define B_END   (BOFF + NSLOT * SLOT_B)     // 138240
#define F2EOFF  B_END
#define F2SOFF  (F2EOFF + N_ * 4)
#define SMEM_DYN (F2SOFF + N_ * 4)          // 154624

// Scratch (device globals — no allocation allowed)
__device__ uint32_t g_Whh[B_ * N_ * HID / 2];       // fp16x2 Wh  [node][h/2]
__device__ float g_f1e[B_ * N_], g_f1s[B_ * N_];    // f1*log2e, 0.2*f1*log2e
__device__ float g_f2e[B_ * N_], g_f2s[B_ * N_];

// ---------------- helpers ----------------
static __device__ __forceinline__ uint32_t smem_u32(const void* p) {
    uint32_t a;
    asm("{ .reg .u64 t; cvta.to.shared.u64 t, %1; cvt.u32.u64 %0, t; }"
        : "=r"(a) : "l"(p));
    return a;
}
static __device__ __forceinline__ float ex2(float x) {
    float y;
    asm("ex2.approx.f32 %0, %1;" : "=f"(y) : "f"(x));
    return y;
}
static __device__ __forceinline__ uint32_t pack2h(float w0, float w1) {
    uint32_t r;
    asm("cvt.rn.f16x2.f32 %0, %1, %2;" : "=r"(r) : "f"(w1), "f"(w0));
    return r;
}
static __device__ __forceinline__ void ldsm4t(uint32_t& r0, uint32_t& r1,
                                              uint32_t& r2, uint32_t& r3,
                                              uint32_t a) {
    asm volatile("ldmatrix.sync.aligned.m8n8.x4.trans.shared.b16 {%0,%1,%2,%3}, [%4];"
                 : "=r"(r0), "=r"(r1), "=r"(r2), "=r"(r3) : "r"(a));
}
static __device__ __forceinline__ void lds64(int2& v, uint32_t a) {
    asm volatile("ld.shared.v2.u32 {%0,%1}, [%2];" : "=r"(v.x), "=r"(v.y) : "r"(a));
}
static __device__ __forceinline__ void mma16816(float* c, const uint32_t* a,
                                                uint32_t b0, uint32_t b1) {
    asm volatile(
        "mma.sync.aligned.m16n8k16.row.col.f32.f16.f16.f32 "
        "{%0,%1,%2,%3}, {%4,%5,%6,%7}, {%8,%9}, {%0,%1,%2,%3};"
        : "+f"(c[0]), "+f"(c[1]), "+f"(c[2]), "+f"(c[3])
        : "r"(a[0]), "r"(a[1]), "r"(a[2]), "r"(a[3]), "r"(b0), "r"(b1));
}
#define CP_ASYNC16(dst, src) \
    asm volatile("cp.async.cg.shared.global [%0], [%1], 16;" :: "r"(dst), "l"(src) : "memory")
#define CP_COMMIT()  asm volatile("cp.async.commit_group;" ::: "memory")
#define CP_WAIT4()   asm volatile("cp.async.wait_group 4;" ::: "memory")

// ---------------------------------------------------------------------------
// Kernel A: Wh = X @ W ; emits packed fp16x2 Wh AND per-node f1/f2 factors.
// ---------------------------------------------------------------------------
__global__ __launch_bounds__(256, 2) void gemm_wh(const float* __restrict__ X,
                                                  const float* __restrict__ W,
                                                  const float* __restrict__ a) {
    __shared__ __align__(16) float Xs[2][64][36];
    __shared__ __align__(16) float Ws[2][32][64];

    const int tid = threadIdx.x;
    const int tx = tid & 15;
    const int ty = tid >> 4;
    const int r0 = blockIdx.x * 64;
    const int xr = tid >> 3, xk = (tid & 7) << 2;
    const int wk = tid >> 4, wh_ = (tid & 15) << 2;

    float acc[4][4];
#pragma unroll
    for (int i = 0; i < 4; i++)
#pragma unroll
        for (int j = 0; j < 4; j++) acc[i][j] = 0.f;

    float4 xv0, xv1, wv0, wv1;
    xv0 = *(const float4*)(X + (size_t)(r0 + xr) * DIN + xk);
    xv1 = *(const float4*)(X + (size_t)(r0 + 32 + xr) * DIN + xk);
    wv0 = *(const float4*)(W + (size_t)wk * HID + wh_);
    wv1 = *(const float4*)(W + (size_t)(16 + wk) * HID + wh_);
    *(float4*)&Xs[0][xr][xk]      = xv0;
    *(float4*)&Xs[0][32 + xr][xk] = xv1;
    *(float4*)&Ws[0][wk][wh_]      = wv0;
    *(float4*)&Ws[0][16 + wk][wh_] = wv1;
    __syncthreads();

    for (int kt = 0; kt < 8; kt++) {
        const int cur = kt & 1, nxt = cur ^ 1;
        if (kt < 7) {
            const int k0 = (kt + 1) * 32;
            xv0 = *(const float4*)(X + (size_t)(r0 + xr) * DIN + k0 + xk);
            xv1 = *(const float4*)(X + (size_t)(r0 + 32 + xr) * DIN + k0 + xk);
            wv0 = *(const float4*)(W + (size_t)(k0 + wk) * HID + wh_);
            wv1 = *(const float4*)(W + (size_t)(k0 + 16 + wk) * HID + wh_);
        }
#pragma unroll
        for (int k = 0; k < 32; k++) {
            float4 wv = *(float4*)&Ws[cur][k][tx << 2];
#pragma unroll
            for (int rr = 0; rr < 4; rr++) {
                float xv = Xs[cur][(ty << 2) + rr][k];
                acc[rr][0] += xv * wv.x;
                acc[rr][1] += xv * wv.y;
                acc[rr][2] += xv * wv.z;
                acc[rr][3] += xv * wv.w;
            }
        }
        if (kt < 7) {
            *(float4*)&Xs[nxt][xr][xk]      = xv0;
            *(float4*)&Xs[nxt][32 + xr][xk] = xv1;
            *(float4*)&Ws[nxt][wk][wh_]      = wv0;
            *(float4*)&Ws[nxt][16 + wk][wh_] = wv1;
        }
        __syncthreads();
    }

    // fp16 Wh output
#pragma unroll
    for (int rr = 0; rr < 4; rr++) {
        const int node = r0 + (ty << 2) + rr;
        size_t o = (size_t)node * 32 + tx * 2;
        *(uint2*)&g_Whh[o] = make_uint2(pack2h(acc[rr][0], acc[rr][1]),
                                        pack2h(acc[rr][2], acc[rr][3]));
    }

    // fused f1/f2 epilogue
    const float4 a1 = *(const float4*)(a + (tx << 2));
    const float4 a2 = *(const float4*)(a + HID + (tx << 2));
    float p1[4], p2[4];
#pragma unroll
    for (int rr = 0; rr < 4; rr++) {
        p1[rr] = acc[rr][0] * a1.x + acc[rr][1] * a1.y +
                 acc[rr][2] * a1.z + acc[rr][3] * a1.w;
        p2[rr] = acc[rr][0] * a2.x + acc[rr][1] * a2.y +
                 acc[rr][2] * a2.z + acc[rr][3] * a2.w;
#pragma unroll
        for (int s = 8; s > 0; s >>= 1) {
            p1[rr] += __shfl_xor_sync(0xffffffffu, p1[rr], s);
            p2[rr] += __shfl_xor_sync(0xffffffffu, p2[rr], s);
        }
    }
    if (tx == 0) {
#pragma unroll
        for (int rr = 0; rr < 4; rr++) {
            const int node = r0 + (ty << 2) + rr;
            g_f1e[node] = p1[rr] * L2E;
            g_f1s[node] = 0.2f * p1[rr] * L2E;
            g_f2e[node] = p2[rr] * L2E;
            g_f2s[node] = 0.2f * p2[rr] * L2E;
        }
    }
}

// ---------------------------------------------------------------------------
// Main kernel: masked-softmax attention * Wh via mma.sync fp16.
// 6-slot cp.async ring, 5 chunks in flight (~92KB/SM outstanding).
// ALL in-loop addresses are incremental (rotating slot registers, advancing
// source pointers) — no t-multiplies. 16 HMMA per chunk.
// ---------------------------------------------------------------------------
__global__ __launch_bounds__(256) void gat_main(const int* __restrict__ adj,
                                                float* __restrict__ out) {
    extern __shared__ __align__(16) char sm[];
    const uint32_t smb = smem_u32(sm);
    float* f2e_s = (float*)(sm + F2EOFF);
    float* f2s_s = (float*)(sm + F2SOFF);

    const int tid = threadIdx.x;
    const int lane = tid & 31, wid = tid >> 5;
    const int g = lane >> 2, tg = lane & 3;
    const int b = blockIdx.x >> 4;
    const int i0 = (blockIdx.x & 15) * TI;
    const int base = b * N_;

    const int r_lo = wid * 16 + g, r_hi = r_lo + 8;

    const int* adjb = adj + (size_t)b * N_ * N_ + (size_t)i0 * N_;
    const uint32_t* whh = g_Whh + (size_t)base * 32;

    // cp.async segment mapping (constant across chunks)
    const int arow = tid >> 3, acol = (tid & 7) * 4;
    const uint32_t a_wslot_off = arow * 144 + acol * 4;       // + q*32*144
    const uint32_t b_wslot_off = (tid >> 3) * 144 + (tid & 7) * 16;

    // stage f2 tables (plain loads; visible after first top-of-loop barrier)
#pragma unroll
    for (int q = 0; q < 2; q++) {
        const int idx = (q * 256 + tid) * 4;
        *(float4*)&f2e_s[idx] = *(const float4*)(g_f2e + base + idx);
        *(float4*)&f2s_s[idx] = *(const float4*)(g_f2s + base + idx);
    }

    // prologue: issue chunks 0..4
    {
        uint32_t aslot = smb + AOFF, bslot = smb + BOFF;
        const int* s0 = adjb + (size_t)arow * N_ + acol;
        const int* s1 = s0 + (size_t)32 * N_;
        const int* s2 = s0 + (size_t)64 * N_;
        const int* s3 = s0 + (size_t)96 * N_;
        const uint32_t* sb = whh + (size_t)(tid >> 3) * 32 + (tid & 7) * 4;
#pragma unroll
        for (int p = 0; p < NSLOT - 1; p++) {
            CP_ASYNC16(aslot + a_wslot_off,                 s0);
            CP_ASYNC16(aslot + a_wslot_off + 32 * 144,      s1);
            CP_ASYNC16(aslot + a_wslot_off + 64 * 144,      s2);
            CP_ASYNC16(aslot + a_wslot_off + 96 * 144,      s3);
            CP_ASYNC16(bslot + b_wslot_off,                 sb);
            CP_COMMIT();
            aslot += SLOT_A; bslot += SLOT_B;
            s0 += CH; s1 += CH; s2 += CH; s3 += CH;
            sb += CH * 32;
        }
    }

    const float f1e_lo = g_f1e[base + i0 + r_lo], f1s_lo = g_f1s[base + i0 + r_lo];
    const float f1e_hi = g_f1e[base + i0 + r_hi], f1s_hi = g_f1s[base + i0 + r_hi];
    float dlo = 0.f, dhi = 0.f;

    float c[8][4];
#pragma unroll
    for (int nt = 0; nt < 8; nt++)
#pragma unroll
        for (int q = 0; q < 4; q++) c[nt][q] = 0.f;

    // rotating/incremental state
    uint32_t a_wr = smb + AOFF + (NSLOT - 1) * SLOT_A;   // write slot for chunk t+5
    uint32_t b_wr = smb + BOFF + (NSLOT - 1) * SLOT_B;
    // read addresses pre-offset for this thread's rows/cols
    const uint32_t co = tg * 8;
    uint32_t a_rd_lo = smb + AOFF + r_lo * 144 + co;     // +32 for j+8; +64 for s=1
    uint32_t a_rd_hi = smb + AOFF + r_hi * 144 + co;
    uint32_t b_rd = smb + BOFF + (lane & 15) * 144 + ((lane >> 4) << 4);
    // source pointers for chunk t+5
    const int* s0 = adjb + (size_t)arow * N_ + acol + (NSLOT - 1) * CH;
    const int* s1 = s0 + (size_t)32 * N_;
    const int* s2 = s0 + (size_t)64 * N_;
    const int* s3 = s0 + (size_t)96 * N_;
    const uint32_t* sb = whh + (size_t)(tid >> 3) * 32 + (tid & 7) * 4 +
                         (size_t)(NSLOT - 1) * CH * 32;
    const float* f2e_p = f2e_s + 2 * tg;
    const float* f2s_p = f2s_s + 2 * tg;

    const uint32_t A_TOP = smb + AOFF + A_END;   // == smb + A_END
    const uint32_t B_TOP = smb + BOFF + NSLOT * SLOT_B;

    for (int t = 0; t < NCH; t++) {
        CP_WAIT4();          // chunk t's copies complete
        __syncthreads();     // visible to all; closes WAR on write slot

        // issue chunk t+5 (slot last read in iteration t-1)
        if (t + NSLOT - 1 < NCH) {
            CP_ASYNC16(a_wr + a_wslot_off,            s0);
            CP_ASYNC16(a_wr + a_wslot_off + 32 * 144, s1);
            CP_ASYNC16(a_wr + a_wslot_off + 64 * 144, s2);
            CP_ASYNC16(a_wr + a_wslot_off + 96 * 144, s3);
            CP_ASYNC16(b_wr + b_wslot_off,            sb);
            s0 += CH; s1 += CH; s2 += CH; s3 += CH;
            sb += CH * 32;
        }
        CP_COMMIT();         // always commit to keep group count aligned
        a_wr += SLOT_A; if (a_wr >= A_TOP) a_wr -= A_END - AOFF;
        b_wr += SLOT_B; if (b_wr >= B_TOP) b_wr -= NSLOT * SLOT_B;

        // stage1: attention-weight A-fragments (fp32 math, one fp16 rounding)
        uint32_t ah[2][4];
#pragma unroll
        for (int s = 0; s < 2; s++) {
            int2 alo0, alo8, ahi0, ahi8;
            lds64(alo0, a_rd_lo + s * 64);
            lds64(alo8, a_rd_lo + s * 64 + 32);
            lds64(ahi0, a_rd_hi + s * 64);
            lds64(ahi8, a_rd_hi + s * 64 + 32);

            const float2 e01 = *(const float2*)(f2e_p + s * 16);
            const float2 e89 = *(const float2*)(f2e_p + s * 16 + 8);
            const float2 s01 = *(const float2*)(f2s_p + s * 16);
            const float2 s89 = *(const float2*)(f2s_p + s * 16 + 8);

            float wl0 = (alo0.x > 0) ? ex2(fmaxf(f1e_lo + e01.x, f1s_lo + s01.x)) : 0.f;
            float wl1 = (alo0.y > 0) ? ex2(fmaxf(f1e_lo + e01.y, f1s_lo + s01.y)) : 0.f;
            float wl8 = (alo8.x > 0) ? ex2(fmaxf(f1e_lo + e89.x, f1s_lo + s89.x)) : 0.f;
            float wl9 = (alo8.y > 0) ? ex2(fmaxf(f1e_lo + e89.y, f1s_lo + s89.y)) : 0.f;
            float wh0 = (ahi0.x > 0) ? ex2(fmaxf(f1e_hi + e01.x, f1s_hi + s01.x)) : 0.f;
            float wh1 = (ahi0.y > 0) ? ex2(fmaxf(f1e_hi + e01.y, f1s_hi + s01.y)) : 0.f;
            float wh8 = (ahi8.x > 0) ? ex2(fmaxf(f1e_hi + e89.x, f1s_hi + s89.x)) : 0.f;
            float wh9 = (ahi8.y > 0) ? ex2(fmaxf(f1e_hi + e89.y, f1s_hi + s89.y)) : 0.f;

            dlo += (wl0 + wl1) + (wl8 + wl9);
            dhi += (wh0 + wh1) + (wh8 + wh9);

            ah[s][0] = pack2h(wl0, wl1);
            ah[s][1] = pack2h(wh0, wh1);
            ah[s][2] = pack2h(wl8, wl9);
            ah[s][3] = pack2h(wh8, wh9);
        }
        a_rd_lo += SLOT_A; if (a_rd_lo >= A_TOP) a_rd_lo -= A_END - AOFF;
        a_rd_hi += SLOT_A; if (a_rd_hi >= A_TOP) a_rd_hi -= A_END - AOFF;
        f2e_p += CH; f2s_p += CH;

        // ldmatrix B fragments + 16 mma per chunk
#pragma unroll
        for (int s = 0; s < 2; s++) {
#pragma unroll
            for (int n16 = 0; n16 < 4; n16++) {
                uint32_t b0, b1, b2, b3;
                ldsm4t(b0, b1, b2, b3, b_rd + s * 16 * 144 + n16 * 32);
                mma16816(c[n16 * 2],     ah[s], b0, b1);
                mma16816(c[n16 * 2 + 1], ah[s], b2, b3);
            }
        }
        b_rd += SLOT_B; if (b_rd >= B_TOP) b_rd -= NSLOT * SLOT_B;
    }

    // ---- softmax denominators (reduce over the 4 lanes sharing a row) ----
    dlo += __shfl_xor_sync(0xffffffffu, dlo, 1);
    dlo += __shfl_xor_sync(0xffffffffu, dlo, 2);
    dhi += __shfl_xor_sync(0xffffffffu, dhi, 1);
    dhi += __shfl_xor_sync(0xffffffffu, dhi, 2);
    const float rlo = __fdividef(1.f, dlo);
    const float rhi = __fdividef(1.f, dhi);

    float* olo = out + (size_t)(base + i0 + r_lo) * HID;
    float* ohi = out + (size_t)(base + i0 + r_hi) * HID;
#pragma unroll
    for (int nt = 0; nt < 8; nt++) {
        *(float2*)&olo[nt * 8 + 2 * tg] = make_float2(c[nt][0] * rlo, c[nt][1] * rlo);
        *(float2*)&ohi[nt * 8 + 2 * tg] = make_float2(c[nt][2] * rhi, c[nt][3] * rhi);
    }
}

// ---------------------------------------------------------------------------
extern "C" void kernel_launch(void* const* d_in, const int* in_sizes, int n_in,
                              void* d_out, int out_size) {
    const float* X  = (const float*)d_in[0];   // node_features [8,2048,256]
    const int*   A  = (const int*)d_in[1];     // adj [8,2048,2048]
    const float* W  = (const float*)d_in[2];   // W [256,64]
    const float* av = (const float*)d_in[3];   // a [128,1]
    float* out = (float*)d_out;                // [8,2048,64] f32

    cudaFuncSetAttribute(gat_main, cudaFuncAttributeMaxDynamicSharedMemorySize,
                         SMEM_DYN);

    gemm_wh<<<(B_ * N_) / 64, 256>>>(X, W, av);
    gat_main<<<dim3(B_ * (N_ / TI)), 256, SMEM_DYN>>>(A, out);
}

// round 10
// speedup vs baseline: 1.1162x; 1.1162x over previous
#include <cuda_runtime.h>
#include <cuda_fp16.h>
#include <cstdint>

#define B_   8
#define N_   2048
#define DIN  256
#define HID  64
#define TI   128
#define CH   32
#define NCH  (N_ / CH)
#define KPG  (NCH / 2)        // chunks per warpgroup (32)
#define L2E  1.4426950408889634f

// dynamic SMEM: per-group 4-slot rings (group g: A ring then B ring)
#define SLOT_A  (128 * 144)                 // adj tile: 128 rows x 32 ints, 144B-padded
#define ABYTES  (8 * SLOT_A)                // 2 groups x 4 slots = 147456
#define SLOT_B  (32 * 144)                  // B tile: 32 nodes x 64 fp16, 144B-padded
#define BBYTES  (8 * SLOT_B)                // 36864
#define F2EOFF  (ABYTES + BBYTES)           // 184320
#define F2SOFF  (F2EOFF + N_ * 4)
#define SMEM_DYN (F2SOFF + N_ * 4)          // 200704

// Scratch (device globals — no allocation allowed)
__device__ uint32_t g_Whh[B_ * N_ * HID / 2];       // fp16x2 Wh  [node][h/2]
__device__ float g_f1e[B_ * N_], g_f1s[B_ * N_];    // f1*log2e, 0.2*f1*log2e
__device__ float g_f2e[B_ * N_], g_f2s[B_ * N_];

// ---------------- helpers ----------------
static __device__ __forceinline__ uint32_t smem_u32(const void* p) {
    uint32_t a;
    asm("{ .reg .u64 t; cvta.to.shared.u64 t, %1; cvt.u32.u64 %0, t; }"
        : "=r"(a) : "l"(p));
    return a;
}
static __device__ __forceinline__ float ex2(float x) {
    float y;
    asm("ex2.approx.f32 %0, %1;" : "=f"(y) : "f"(x));
    return y;
}
static __device__ __forceinline__ uint32_t pack2h(float w0, float w1) {
    uint32_t r;
    asm("cvt.rn.f16x2.f32 %0, %1, %2;" : "=r"(r) : "f"(w1), "f"(w0));
    return r;
}
static __device__ __forceinline__ void ldsm4t(uint32_t& r0, uint32_t& r1,
                                              uint32_t& r2, uint32_t& r3,
                                              uint32_t a) {
    asm volatile("ldmatrix.sync.aligned.m8n8.x4.trans.shared.b16 {%0,%1,%2,%3}, [%4];"
                 : "=r"(r0), "=r"(r1), "=r"(r2), "=r"(r3) : "r"(a));
}
static __device__ __forceinline__ void lds64(int2& v, uint32_t a) {
    asm volatile("ld.shared.v2.u32 {%0,%1}, [%2];" : "=r"(v.x), "=r"(v.y) : "r"(a));
}
static __device__ __forceinline__ void mma16816(float* c, const uint32_t* a,
                                                uint32_t b0, uint32_t b1) {
    asm volatile(
        "mma.sync.aligned.m16n8k16.row.col.f32.f16.f16.f32 "
        "{%0,%1,%2,%3}, {%4,%5,%6,%7}, {%8,%9}, {%0,%1,%2,%3};"
        : "+f"(c[0]), "+f"(c[1]), "+f"(c[2]), "+f"(c[3])
        : "r"(a[0]), "r"(a[1]), "r"(a[2]), "r"(a[3]), "r"(b0), "r"(b1));
}
#define CP_ASYNC16(dst, src) \
    asm volatile("cp.async.cg.shared.global [%0], [%1], 16;" :: "r"(dst), "l"(src) : "memory")
#define CP_COMMIT()  asm volatile("cp.async.commit_group;" ::: "memory")
#define CP_WAIT2()   asm volatile("cp.async.wait_group 2;" ::: "memory")
#define CP_WAIT0()   asm volatile("cp.async.wait_group 0;" ::: "memory")
#define GBAR(id)     asm volatile("bar.sync %0, 256;" :: "r"(id) : "memory")

// ---------------------------------------------------------------------------
// Kernel A: Wh = X @ W ; emits packed fp16x2 Wh AND per-node f1/f2 factors.
// ---------------------------------------------------------------------------
__global__ __launch_bounds__(256, 2) void gemm_wh(const float* __restrict__ X,
                                                  const float* __restrict__ W,
                                                  const float* __restrict__ a) {
    __shared__ __align__(16) float Xs[2][64][36];
    __shared__ __align__(16) float Ws[2][32][64];

    const int tid = threadIdx.x;
    const int tx = tid & 15;
    const int ty = tid >> 4;
    const int r0 = blockIdx.x * 64;
    const int xr = tid >> 3, xk = (tid & 7) << 2;
    const int wk = tid >> 4, wh_ = (tid & 15) << 2;

    float acc[4][4];
#pragma unroll
    for (int i = 0; i < 4; i++)
#pragma unroll
        for (int j = 0; j < 4; j++) acc[i][j] = 0.f;

    float4 xv0, xv1, wv0, wv1;
    xv0 = *(const float4*)(X + (size_t)(r0 + xr) * DIN + xk);
    xv1 = *(const float4*)(X + (size_t)(r0 + 32 + xr) * DIN + xk);
    wv0 = *(const float4*)(W + (size_t)wk * HID + wh_);
    wv1 = *(const float4*)(W + (size_t)(16 + wk) * HID + wh_);
    *(float4*)&Xs[0][xr][xk]      = xv0;
    *(float4*)&Xs[0][32 + xr][xk] = xv1;
    *(float4*)&Ws[0][wk][wh_]      = wv0;
    *(float4*)&Ws[0][16 + wk][wh_] = wv1;
    __syncthreads();

    for (int kt = 0; kt < 8; kt++) {
        const int cur = kt & 1, nxt = cur ^ 1;
        if (kt < 7) {
            const int k0 = (kt + 1) * 32;
            xv0 = *(const float4*)(X + (size_t)(r0 + xr) * DIN + k0 + xk);
            xv1 = *(const float4*)(X + (size_t)(r0 + 32 + xr) * DIN + k0 + xk);
            wv0 = *(const float4*)(W + (size_t)(k0 + wk) * HID + wh_);
            wv1 = *(const float4*)(W + (size_t)(k0 + 16 + wk) * HID + wh_);
        }
#pragma unroll
        for (int k = 0; k < 32; k++) {
            float4 wv = *(float4*)&Ws[cur][k][tx << 2];
#pragma unroll
            for (int rr = 0; rr < 4; rr++) {
                float xv = Xs[cur][(ty << 2) + rr][k];
                acc[rr][0] += xv * wv.x;
                acc[rr][1] += xv * wv.y;
                acc[rr][2] += xv * wv.z;
                acc[rr][3] += xv * wv.w;
            }
        }
        if (kt < 7) {
            *(float4*)&Xs[nxt][xr][xk]      = xv0;
            *(float4*)&Xs[nxt][32 + xr][xk] = xv1;
            *(float4*)&Ws[nxt][wk][wh_]      = wv0;
            *(float4*)&Ws[nxt][16 + wk][wh_] = wv1;
        }
        __syncthreads();
    }

    // fp16 Wh output
#pragma unroll
    for (int rr = 0; rr < 4; rr++) {
        const int node = r0 + (ty << 2) + rr;
        size_t o = (size_t)node * 32 + tx * 2;
        *(uint2*)&g_Whh[o] = make_uint2(pack2h(acc[rr][0], acc[rr][1]),
                                        pack2h(acc[rr][2], acc[rr][3]));
    }

    // fused f1/f2 epilogue
    const float4 a1 = *(const float4*)(a + (tx << 2));
    const float4 a2 = *(const float4*)(a + HID + (tx << 2));
    float p1[4], p2[4];
#pragma unroll
    for (int rr = 0; rr < 4; rr++) {
        p1[rr] = acc[rr][0] * a1.x + acc[rr][1] * a1.y +
                 acc[rr][2] * a1.z + acc[rr][3] * a1.w;
        p2[rr] = acc[rr][0] * a2.x + acc[rr][1] * a2.y +
                 acc[rr][2] * a2.z + acc[rr][3] * a2.w;
#pragma unroll
        for (int s = 8; s > 0; s >>= 1) {
            p1[rr] += __shfl_xor_sync(0xffffffffu, p1[rr], s);
            p2[rr] += __shfl_xor_sync(0xffffffffu, p2[rr], s);
        }
    }
    if (tx == 0) {
#pragma unroll
        for (int rr = 0; rr < 4; rr++) {
            const int node = r0 + (ty << 2) + rr;
            g_f1e[node] = p1[rr] * L2E;
            g_f1s[node] = 0.2f * p1[rr] * L2E;
            g_f2e[node] = p2[rr] * L2E;
            g_f2s[node] = 0.2f * p2[rr] * L2E;
        }
    }
}

// ---------------------------------------------------------------------------
// Main kernel: masked-softmax attention * Wh via mma.sync fp16.
// 512 threads = TWO independent 8-warp pipelines per CTA (named barriers):
// group 0 -> even chunks, group 1 -> odd chunks, each with a private 4-slot
// cp.async ring (R8-proven structure). Partials merged via SMEM at the end.
// ---------------------------------------------------------------------------
__global__ __launch_bounds__(512) void gat_main(const int* __restrict__ adj,
                                                float* __restrict__ out) {
    extern __shared__ __align__(16) char sm[];
    const uint32_t smb = smem_u32(sm);
    float* f2e_s = (float*)(sm + F2EOFF);
    float* f2s_s = (float*)(sm + F2SOFF);

    const int tid = threadIdx.x;
    const int wg = tid >> 8;                 // warpgroup 0/1
    const int wtid = tid & 255;
    const int lane = tid & 31, w8 = wtid >> 5;   // warp-in-group 0..7
    const int g = lane >> 2, tg = lane & 3;
    const int b = blockIdx.x >> 4;
    const int i0 = (blockIdx.x & 15) * TI;
    const int base = b * N_;

    const int r_lo = w8 * 16 + g, r_hi = r_lo + 8;

    const int* adjb = adj + (size_t)b * N_ * N_ + (size_t)i0 * N_;
    const uint32_t* whh = g_Whh + (size_t)base * 32;

    // group-private ring bases
    const uint32_t agb = smb + wg * 4 * SLOT_A;
    const uint32_t bgb = smb + ABYTES + wg * 4 * SLOT_B;

    // cp.async segment mapping (within group)
    const int arow = wtid >> 3, acol = (wtid & 7) * 4;
    const uint32_t a_woff = arow * 144 + acol * 4;           // +q*32*144
    const uint32_t b_woff = (wtid >> 3) * 144 + (wtid & 7) * 16;

    // stage f2 tables (512 threads: one float4 each per table)
    {
        const int idx = tid * 4;
        *(float4*)&f2e_s[idx] = *(const float4*)(g_f2e + base + idx);
        *(float4*)&f2s_s[idx] = *(const float4*)(g_f2s + base + idx);
    }

    // prologue: each group issues its chunks k=0,1,2 (global ch = 2k+wg)
#pragma unroll
    for (int p = 0; p < 3; p++) {
        const int ch = 2 * p + wg;
        const uint32_t aslot = agb + p * SLOT_A;
        const uint32_t bslot = bgb + p * SLOT_B;
#pragma unroll
        for (int q = 0; q < 4; q++) {
            const int row = arow + q * 32;
            CP_ASYNC16(aslot + a_woff + q * 32 * 144,
                       adjb + (size_t)row * N_ + ch * CH + acol);
        }
        CP_ASYNC16(bslot + b_woff, whh + (size_t)(ch * CH + (wtid >> 3)) * 32 + (wtid & 7) * 4);
        CP_COMMIT();
    }
    __syncthreads();   // f2 tables visible to both groups

    const float f1e_lo = g_f1e[base + i0 + r_lo], f1s_lo = g_f1s[base + i0 + r_lo];
    const float f1e_hi = g_f1e[base + i0 + r_hi], f1s_hi = g_f1s[base + i0 + r_hi];
    float dlo = 0.f, dhi = 0.f;

    float c[8][4];
#pragma unroll
    for (int nt = 0; nt < 8; nt++)
#pragma unroll
        for (int q = 0; q < 4; q++) c[nt][q] = 0.f;

    const uint32_t bar_id = wg + 1;

    for (int k = 0; k < KPG; k++) {
        CP_WAIT2();          // this group's chunk k complete
        GBAR(bar_id);        // group-local visibility; closes WAR on slot (k+3)&3

        // issue chunk k+3 (global ch = 2(k+3)+wg)
        if (k + 3 < KPG) {
            const int ch = 2 * (k + 3) + wg;
            const uint32_t aslot = agb + ((k + 3) & 3) * SLOT_A;
            const uint32_t bslot = bgb + ((k + 3) & 3) * SLOT_B;
#pragma unroll
            for (int q = 0; q < 4; q++) {
                const int row = arow + q * 32;
                CP_ASYNC16(aslot + a_woff + q * 32 * 144,
                           adjb + (size_t)row * N_ + ch * CH + acol);
            }
            CP_ASYNC16(bslot + b_woff,
                       whh + (size_t)(ch * CH + (wtid >> 3)) * 32 + (wtid & 7) * 4);
        }
        CP_COMMIT();         // keep group counter aligned

        const uint32_t adjslot = agb + (k & 3) * SLOT_A;
        const uint32_t bslot   = bgb + (k & 3) * SLOT_B;
        const int jb0 = (2 * k + wg) * CH;

        // stage1: attention-weight A-fragments (fp32 math, one fp16 rounding)
        uint32_t ah[2][4];
#pragma unroll
        for (int s = 0; s < 2; s++) {
            const int co = s * 64 + tg * 8;
            int2 alo0, alo8, ahi0, ahi8;
            lds64(alo0, adjslot + r_lo * 144 + co);
            lds64(alo8, adjslot + r_lo * 144 + co + 32);
            lds64(ahi0, adjslot + r_hi * 144 + co);
            lds64(ahi8, adjslot + r_hi * 144 + co + 32);

            const int jb = jb0 + s * 16 + 2 * tg;
            const float2 e01 = *(const float2*)&f2e_s[jb];
            const float2 e89 = *(const float2*)&f2e_s[jb + 8];
            const float2 s01 = *(const float2*)&f2s_s[jb];
            const float2 s89 = *(const float2*)&f2s_s[jb + 8];

            float wl0 = (alo0.x > 0) ? ex2(fmaxf(f1e_lo + e01.x, f1s_lo + s01.x)) : 0.f;
            float wl1 = (alo0.y > 0) ? ex2(fmaxf(f1e_lo + e01.y, f1s_lo + s01.y)) : 0.f;
            float wl8 = (alo8.x > 0) ? ex2(fmaxf(f1e_lo + e89.x, f1s_lo + s89.x)) : 0.f;
            float wl9 = (alo8.y > 0) ? ex2(fmaxf(f1e_lo + e89.y, f1s_lo + s89.y)) : 0.f;
            float wh0 = (ahi0.x > 0) ? ex2(fmaxf(f1e_hi + e01.x, f1s_hi + s01.x)) : 0.f;
            float wh1 = (ahi0.y > 0) ? ex2(fmaxf(f1e_hi + e01.y, f1s_hi + s01.y)) : 0.f;
            float wh8 = (ahi8.x > 0) ? ex2(fmaxf(f1e_hi + e89.x, f1s_hi + s89.x)) : 0.f;
            float wh9 = (ahi8.y > 0) ? ex2(fmaxf(f1e_hi + e89.y, f1s_hi + s89.y)) : 0.f;

            dlo += (wl0 + wl1) + (wl8 + wl9);
            dhi += (wh0 + wh1) + (wh8 + wh9);

            ah[s][0] = pack2h(wl0, wl1);
            ah[s][1] = pack2h(wh0, wh1);
            ah[s][2] = pack2h(wl8, wl9);
            ah[s][3] = pack2h(wh8, wh9);
        }

        // ldmatrix B fragments + 16 mma per chunk
        const uint32_t b_rd = bslot + (lane & 15) * 144 + ((lane >> 4) << 4);
#pragma unroll
        for (int s = 0; s < 2; s++) {
#pragma unroll
            for (int n16 = 0; n16 < 4; n16++) {
                uint32_t b0, b1, b2, b3;
                ldsm4t(b0, b1, b2, b3, b_rd + s * 16 * 144 + n16 * 32);
                mma16816(c[n16 * 2],     ah[s], b0, b1);
                mma16816(c[n16 * 2 + 1], ah[s], b2, b3);
            }
        }
    }

    // ---- merge the two groups' partials ----
    // quad-reduce denominators first
    dlo += __shfl_xor_sync(0xffffffffu, dlo, 1);
    dlo += __shfl_xor_sync(0xffffffffu, dlo, 2);
    dhi += __shfl_xor_sync(0xffffffffu, dhi, 1);
    dhi += __shfl_xor_sync(0xffffffffu, dhi, 2);

    CP_WAIT0();
    __syncthreads();   // both pipelines done; SMEM ring reusable

    float* cbuf = (float*)sm;                   // 128 x 64 fp32 = 32KB
    float* dbuf = (float*)(sm + 32768);         // 128 floats

    if (wg == 1) {
#pragma unroll
        for (int nt = 0; nt < 8; nt++) {
            const int col = nt * 8 + 2 * tg;
            cbuf[r_lo * 64 + col]     = c[nt][0];
            cbuf[r_lo * 64 + col + 1] = c[nt][1];
            cbuf[r_hi * 64 + col]     = c[nt][2];
            cbuf[r_hi * 64 + col + 1] = c[nt][3];
        }
        if (tg == 0) {
            dbuf[r_lo] = dlo;
            dbuf[r_hi] = dhi;
        }
    }
    __syncthreads();

    if (wg == 0) {
        const float rlo = __fdividef(1.f, dlo + dbuf[r_lo]);
        const float rhi = __fdividef(1.f, dhi + dbuf[r_hi]);
        float* olo = out + (size_t)(base + i0 + r_lo) * HID;
        float* ohi = out + (size_t)(base + i0 + r_hi) * HID;
#pragma unroll
        for (int nt = 0; nt < 8; nt++) {
            const int col = nt * 8 + 2 * tg;
            *(float2*)&olo[col] = make_float2((c[nt][0] + cbuf[r_lo * 64 + col]) * rlo,
                                              (c[nt][1] + cbuf[r_lo * 64 + col + 1]) * rlo);
            *(float2*)&ohi[col] = make_float2((c[nt][2] + cbuf[r_hi * 64 + col]) * rhi,
                                              (c[nt][3] + cbuf[r_hi * 64 + col + 1]) * rhi);
        }
    }
}

// ---------------------------------------------------------------------------
extern "C" void kernel_launch(void* const* d_in, const int* in_sizes, int n_in,
                              void* d_out, int out_size) {
    const float* X  = (const float*)d_in[0];   // node_features [8,2048,256]
    const int*   A  = (const int*)d_in[1];     // adj [8,2048,2048]
    const float* W  = (const float*)d_in[2];   // W [256,64]
    const float* av = (const float*)d_in[3];   // a [128,1]
    float* out = (float*)d_out;                // [8,2048,64] f32

    cudaFuncSetAttribute(gat_main, cudaFuncAttributeMaxDynamicSharedMemorySize,
                         SMEM_DYN);

    gemm_wh<<<(B_ * N_) / 64, 256>>>(X, W, av);
    gat_main<<<dim3(B_ * (N_ / TI)), 512, SMEM_DYN>>>(A, out);
}